// round 4
// baseline (speedup 1.0000x reference)
#include <cuda_runtime.h>
#include <math.h>

#define TPB   256
#define ROWS  16      // h-rows per CTA tile
#define PCH   128     // points per CTA chunk (split 2 x 64 across warp groups)
#define PHALF 64

typedef unsigned long long u64;

__device__ __forceinline__ float fast_exp2(float x) {
    float y;
    asm("ex2.approx.ftz.f32 %0, %1;" : "=f"(y) : "f"(x));
    return y;
}
__device__ __forceinline__ u64 pack2(float a, float b) {
    u64 r;
    asm("mov.b64 %0, {%1, %2};" : "=l"(r) : "f"(a), "f"(b));
    return r;
}
__device__ __forceinline__ void unpack2(u64 v, float& a, float& b) {
    asm("mov.b64 {%0, %1}, %2;" : "=f"(a), "=f"(b) : "l"(v));
}
__device__ __forceinline__ u64 fma2(u64 a, u64 b, u64 c) {
    u64 d;
    asm("fma.rn.f32x2 %0, %1, %2, %3;" : "=l"(d) : "l"(a), "l"(b), "l"(c));
    return d;
}
__device__ __forceinline__ u64 mul2(u64 a, u64 b) {
    u64 d;
    asm("mul.rn.f32x2 %0, %1, %2;" : "=l"(d) : "l"(a), "l"(b));
    return d;
}
__device__ __forceinline__ u64 add2(u64 a, u64 b) {
    u64 d;
    asm("add.rn.f32x2 %0, %1, %2;" : "=l"(d) : "l"(a), "l"(b));
    return d;
}

__global__ void __launch_bounds__(TPB, 2)
splat2d_grp_kernel(const float* __restrict__ coords,   // [N,P,2]
                   const float* __restrict__ values,   // [N,P,3]
                   const float* __restrict__ sigma,    // [N,1]
                   float* __restrict__ out,            // [N,3,H,W]
                   int P, int H, int W) {
    __shared__ ulonglong2 svd01[PCH];        // {(v0,v0),(v1,v1)}
    __shared__ u64        svd2 [PCH];        // (v2,v2)
    __shared__ float      sbx  [PCH];        // a * px   (a = sqrt(-s))
    __shared__ float      sey  [PCH][ROWS];  // separable y-factor
    __shared__ ulonglong2 comb [12][128];    // group-1 partials (12 x u64x2 per col)

    const int n      = blockIdx.z;
    const int p0     = blockIdx.y * PCH;
    const int tile_r = blockIdx.x * ROWS;

    const float* cb = coords + (size_t)n * P * 2;
    const float* vb = values + (size_t)n * P * 3;
    const float2* cb2 = (const float2*)cb;

    const float sg = sigma[n];
    const float s  = (-0.5f / (sg * sg)) * 1.4426950408889634f;  // w = exp2(s*d2)
    const float a  = sqrtf(-s);                                  // s*d2 = -(a*d)^2

    // ---- stage point data ----
    if (threadIdx.x < PCH) {
        const int p = p0 + threadIdx.x;
        const float v0 = vb[p * 3 + 0];
        const float v1 = vb[p * 3 + 1];
        const float v2 = vb[p * 3 + 2];
        svd01[threadIdx.x] = make_ulonglong2(pack2(v0, v0), pack2(v1, v1));
        svd2 [threadIdx.x] = pack2(v2, v2);
        sbx  [threadIdx.x] = a * cb2[p].x;
    }
    for (int e = threadIdx.x; e < PCH * ROWS; e += TPB) {
        const int p = e >> 4;                 // ROWS == 16
        const int r = e & (ROWS - 1);
        const float by = a * cb2[p0 + p].y;
        const float dy = fmaf(a, (float)(tile_r + r), -by);
        sey[p][r] = fast_exp2(-dy * dy);
    }
    __syncthreads();

    // ---- warp-group split: g=0 -> points [0,64), g=1 -> [64,128) ----
    const int g     = threadIdx.x >> 7;       // 0 or 1
    const int w_col = threadIdx.x & 127;      // lanes contiguous -> LDS broadcast
    const float fx  = (float)w_col;
    const float afx = a * fx;

    u64 acc[3][8];
    #pragma unroll
    for (int c = 0; c < 3; ++c)
        #pragma unroll
        for (int j = 0; j < 8; ++j) acc[c][j] = 0ULL;

    const int pbeg = g * PHALF;
    #pragma unroll 2
    for (int p = pbeg; p < pbeg + PHALF; ++p) {
        const float dx = afx - sbx[p];                   // LDS.32 broadcast
        const float ex = fast_exp2(-dx * dx);
        const u64 exd  = pack2(ex, ex);

        const ulonglong2 v01 = svd01[p];                 // LDS.128 broadcast
        const u64        v2  = svd2[p];                  // LDS.64  broadcast
        const u64 u0 = mul2(exd, v01.x);
        const u64 u1 = mul2(exd, v01.y);
        const u64 u2 = mul2(exd, v2);

        const ulonglong2* eyp = reinterpret_cast<const ulonglong2*>(&sey[p][0]);
        #pragma unroll
        for (int jj = 0; jj < 4; ++jj) {
            const ulonglong2 q = eyp[jj];                // LDS.128: 4 rows of ey
            acc[0][2*jj]   = fma2(u0, q.x, acc[0][2*jj]);
            acc[1][2*jj]   = fma2(u1, q.x, acc[1][2*jj]);
            acc[2][2*jj]   = fma2(u2, q.x, acc[2][2*jj]);
            acc[0][2*jj+1] = fma2(u0, q.y, acc[0][2*jj+1]);
            acc[1][2*jj+1] = fma2(u1, q.y, acc[1][2*jj+1]);
            acc[2][2*jj+1] = fma2(u2, q.y, acc[2][2*jj+1]);
        }
    }

    // ---- combine the two groups through shared ----
    __syncthreads();
    if (g == 1) {
        #pragma unroll
        for (int c = 0; c < 3; ++c)
            #pragma unroll
            for (int j = 0; j < 4; ++j)
                comb[c * 4 + j][w_col] = make_ulonglong2(acc[c][2*j], acc[c][2*j+1]);
    }
    __syncthreads();

    if (g == 0) {
        #pragma unroll
        for (int c = 0; c < 3; ++c)
            #pragma unroll
            for (int j = 0; j < 4; ++j) {
                const ulonglong2 q = comb[c * 4 + j][w_col];
                acc[c][2*j]   = add2(acc[c][2*j],   q.x);
                acc[c][2*j+1] = add2(acc[c][2*j+1], q.y);
            }

        const size_t hw = (size_t)H * W;
        #pragma unroll
        for (int c = 0; c < 3; ++c) {
            float* ob = out + ((size_t)n * 3 + c) * hw + (size_t)tile_r * W + w_col;
            #pragma unroll
            for (int j = 0; j < 8; ++j) {
                float lo, hi;
                unpack2(acc[c][j], lo, hi);
                atomicAdd(ob + (size_t)(2 * j) * W,     lo);
                atomicAdd(ob + (size_t)(2 * j + 1) * W, hi);
            }
        }
    }
}

extern "C" void kernel_launch(void* const* d_in, const int* in_sizes, int n_in,
                              void* d_out, int out_size) {
    const float* coords = (const float*)d_in[0];   // [N,P,2]
    const float* values = (const float*)d_in[1];   // [N,P,C]
    const float* sigma  = (const float*)d_in[2];   // [N,1]

    const int N = in_sizes[2];
    const int P = in_sizes[0] / (2 * N);
    const int C = in_sizes[1] / (N * P);
    const int HW = out_size / (N * C);
    int W = 1;
    while (W * W < HW) ++W;                        // square grid (H == W)
    const int H = HW / W;

    float* out = (float*)d_out;
    cudaMemsetAsync(d_out, 0, (size_t)out_size * sizeof(float), 0);

    dim3 grid(H / ROWS, P / PCH, N);               // 8 x 8 x 4 = 256 CTAs
    splat2d_grp_kernel<<<grid, TPB>>>(coords, values, sigma, out, P, H, W);
}

// round 6
// speedup vs baseline: 1.2909x; 1.2909x over previous
#include <cuda_runtime.h>
#include <cuda_fp16.h>
#include <cstdint>
#include <math.h>

#define TPB 256

static __device__ __forceinline__ uint32_t s2u(const void* p) {
    uint32_t a;
    asm("{ .reg .u64 t; cvta.to.shared.u64 t, %1; cvt.u32.u64 %0, t; }" : "=r"(a) : "l"(p));
    return a;
}
static __device__ __forceinline__ float fast_exp2(float x) {
    float y; asm("ex2.approx.ftz.f32 %0, %1;" : "=f"(y) : "f"(x)); return y;
}
static __device__ __forceinline__ uint32_t pack_h2(float lo, float hi) {
    uint32_t u;
    asm("cvt.rn.f16x2.f32 %0, %1, %2;" : "=r"(u) : "f"(hi), "f"(lo));  // d.lo = %2
    return u;
}
static __device__ __forceinline__ uint32_t sw128(uint32_t off) {
    return off ^ ((off >> 3) & 0x70);
}
static __device__ __forceinline__ void ldsm_x4(uint32_t addr, uint32_t& r0, uint32_t& r1,
                                               uint32_t& r2, uint32_t& r3) {
    asm volatile("ldmatrix.sync.aligned.m8n8.x4.shared.b16 {%0,%1,%2,%3}, [%4];"
                 : "=r"(r0), "=r"(r1), "=r"(r2), "=r"(r3) : "r"(addr));
}
static __device__ __forceinline__ void mma16816(float* c, uint32_t a0, uint32_t a1,
                                                uint32_t a2, uint32_t a3,
                                                uint32_t b0, uint32_t b1) {
    asm volatile(
        "mma.sync.aligned.m16n8k16.row.col.f32.f16.f16.f32 "
        "{%0,%1,%2,%3}, {%4,%5,%6,%7}, {%8,%9}, {%0,%1,%2,%3};"
        : "+f"(c[0]), "+f"(c[1]), "+f"(c[2]), "+f"(c[3])
        : "r"(a0), "r"(a1), "r"(a2), "r"(a3), "r"(b0), "r"(b1));
}

// CTA = (kchunk of 64 points, channel c, batch n).
// D[128h x 128w] += sum_p ey[h,p] * (ex[w,p] * v[p,c]),  fp16 in, fp32 accum.
__global__ void __launch_bounds__(TPB)
splat2d_hmma_kernel(const float* __restrict__ coords,   // [N,P,2]
                    const float* __restrict__ values,   // [N,P,3]
                    const float* __restrict__ sigma,    // [N,1]
                    float* __restrict__ out,            // [N,3,128,128]
                    int P) {
    __shared__ float bx[64], by[64], vc[64];
    __shared__ __align__(1024) char At[128 * 128];   // ey tile: 128h x 64p fp16, SW128
    __shared__ __align__(1024) char Bt[128 * 128];   // (ex*v) : 128w x 64p fp16, SW128

    const int tid  = threadIdx.x;
    const int kp   = blockIdx.x;
    const int c    = blockIdx.y;
    const int n    = blockIdx.z;
    const int p0   = kp * 64;

    const float sg = sigma[n];
    const float a_ = sqrtf(0.72134752044448169f) / sg;   // sqrt(log2(e)/2)/sigma

    const float2* cb2 = (const float2*)coords + (size_t)n * P;
    const float*  vb  = values + (size_t)n * P * 3;

    if (tid < 64) {
        const float2 cd = cb2[p0 + tid];
        bx[tid] = a_ * cd.x;
        by[tid] = a_ * cd.y;
        vc[tid] = vb[(p0 + tid) * 3 + c];
    }
    __syncthreads();

    const uint32_t Abase = s2u(At);
    const uint32_t Bbase = s2u(Bt);

    // ---- A tile: ey[h][p] ----
    for (int task = tid; task < 1024; task += TPB) {
        const int h = task >> 3, pg = task & 7;
        const float ah = a_ * (float)h;
        float e[8];
        #pragma unroll
        for (int i = 0; i < 8; ++i) {
            const float d = ah - by[pg * 8 + i];
            e[i] = fast_exp2(-d * d);
        }
        const uint32_t q0 = pack_h2(e[0], e[1]);
        const uint32_t q1 = pack_h2(e[2], e[3]);
        const uint32_t q2 = pack_h2(e[4], e[5]);
        const uint32_t q3 = pack_h2(e[6], e[7]);
        asm volatile("st.shared.v4.b32 [%0], {%1,%2,%3,%4};"
                     :: "r"(Abase + sw128((uint32_t)(h * 128 + pg * 16))),
                        "r"(q0), "r"(q1), "r"(q2), "r"(q3));
    }
    // ---- B tile: (ex * vc)[w][p] ----
    for (int task = tid; task < 1024; task += TPB) {
        const int w = task >> 3, pg = task & 7;
        const float aw = a_ * (float)w;
        float m[8];
        #pragma unroll
        for (int i = 0; i < 8; ++i) {
            const float d = aw - bx[pg * 8 + i];
            m[i] = fast_exp2(-d * d) * vc[pg * 8 + i];
        }
        const uint32_t q0 = pack_h2(m[0], m[1]);
        const uint32_t q1 = pack_h2(m[2], m[3]);
        const uint32_t q2 = pack_h2(m[4], m[5]);
        const uint32_t q3 = pack_h2(m[6], m[7]);
        asm volatile("st.shared.v4.b32 [%0], {%1,%2,%3,%4};"
                     :: "r"(Bbase + sw128((uint32_t)(w * 128 + pg * 16))),
                        "r"(q0), "r"(q1), "r"(q2), "r"(q3));
    }
    __syncthreads();

    // ---- consumer: 8 warps, warp tile 32h x 64w ----
    const int wid  = tid >> 5;
    const int lane = tid & 31;
    const int h0   = (wid & 3) * 32;
    const int w0   = (wid >> 2) * 64;

    float acc[2][8][4];
    #pragma unroll
    for (int mb = 0; mb < 2; ++mb)
        #pragma unroll
        for (int nb = 0; nb < 8; ++nb)
            #pragma unroll
            for (int j = 0; j < 4; ++j) acc[mb][nb][j] = 0.f;

    // A lane addressing: rows h0+mb*16+(lane%16), 16B col block = kbyte + (lane/16)*16
    const int a_row = lane & 15;
    const int a_kb  = (lane >> 4) << 4;
    // B lane addressing: rows w0+nb16*16 + ((lane>>4)&1)*8 + (lane&7), col = kbyte + ((lane>>3)&1)*16
    const int b_row = (((lane >> 4) & 1) << 3) + (lane & 7);
    const int b_kb  = ((lane >> 3) & 1) << 4;

    #pragma unroll
    for (int ks = 0; ks < 4; ++ks) {
        const uint32_t kbyte = ks * 32;   // 16 f16 per K-step

        uint32_t a[2][4];
        #pragma unroll
        for (int mb = 0; mb < 2; ++mb) {
            const uint32_t row = (uint32_t)(h0 + mb * 16 + a_row);
            ldsm_x4(Abase + sw128(row * 128 + kbyte + a_kb),
                    a[mb][0], a[mb][1], a[mb][2], a[mb][3]);
        }
        uint32_t b[4][4];
        #pragma unroll
        for (int nb16 = 0; nb16 < 4; ++nb16) {
            const uint32_t row = (uint32_t)(w0 + nb16 * 16 + b_row);
            ldsm_x4(Bbase + sw128(row * 128 + kbyte + b_kb),
                    b[nb16][0], b[nb16][1], b[nb16][2], b[nb16][3]);
        }
        #pragma unroll
        for (int mb = 0; mb < 2; ++mb)
            #pragma unroll
            for (int nb = 0; nb < 8; ++nb)
                mma16816(acc[mb][nb],
                         a[mb][0], a[mb][1], a[mb][2], a[mb][3],
                         b[nb >> 1][(nb & 1) ? 2 : 0], b[nb >> 1][(nb & 1) ? 3 : 1]);
    }

    // ---- epilogue: atomic-add partials ----
    const int r  = lane >> 2;
    const int c2 = (lane & 3) * 2;
    float* outn = out + (((size_t)n * 3 + c) << 14);
    #pragma unroll
    for (int mb = 0; mb < 2; ++mb) {
        #pragma unroll
        for (int nb = 0; nb < 8; ++nb) {
            const int hh = h0 + mb * 16 + r;
            const int ww = w0 + nb * 8 + c2;
            float* p = outn + hh * 128 + ww;
            atomicAdd(p,             acc[mb][nb][0]);
            atomicAdd(p + 1,         acc[mb][nb][1]);
            atomicAdd(p + 8 * 128,     acc[mb][nb][2]);
            atomicAdd(p + 8 * 128 + 1, acc[mb][nb][3]);
        }
    }
}

extern "C" void kernel_launch(void* const* d_in, const int* in_sizes, int n_in,
                              void* d_out, int out_size) {
    const float* coords = (const float*)d_in[0];   // [N,P,2]
    const float* values = (const float*)d_in[1];   // [N,P,C]
    const float* sigma  = (const float*)d_in[2];   // [N,1]

    const int N = in_sizes[2];
    const int P = in_sizes[0] / (2 * N);           // 1024
    float* out = (float*)d_out;

    cudaMemsetAsync(d_out, 0, (size_t)out_size * sizeof(float), 0);

    dim3 grid(P / 64, 3, N);                       // 16 x 3 x 4 = 192 CTAs
    splat2d_hmma_kernel<<<grid, TPB>>>(coords, values, sigma, out, P);
}